// round 3
// baseline (speedup 1.0000x reference)
#include <cuda_runtime.h>
#include <cuda_bf16.h>

// NeRF renderer: 16384 rays, 64 coarse + 64 importance samples, 3->64->{1,3} MLP.
// One warp per ray, contiguous chunk ownership, warp-shuffle scans.
// MLP math uses Blackwell packed f32x2 FMA (FFMA2) with duplicated weights in
// shared so packed operands come straight from LDS.128 broadcasts.

#define N_RAYS     16384
#define WARPS_PB   8
#define BLOCKS     (N_RAYS / WARPS_PB)
#define FULLMASK   0xffffffffu

typedef unsigned long long u64;

__device__ __forceinline__ u64 pk2(float lo, float hi) {
    u64 r;
    asm("mov.b64 %0, {%1, %2};" : "=l"(r) : "f"(lo), "f"(hi));
    return r;
}
__device__ __forceinline__ void upk2(u64 v, float& lo, float& hi) {
    asm("mov.b64 {%0, %1}, %2;" : "=f"(lo), "=f"(hi) : "l"(v));
}
__device__ __forceinline__ u64 ffma2(u64 a, u64 b, u64 c) {
    u64 d;
    asm("fma.rn.f32x2 %0, %1, %2, %3;" : "=l"(d) : "l"(a), "l"(b), "l"(c));
    return d;
}
__device__ __forceinline__ u64 relu2(u64 x) {
    float lo, hi;
    upk2(x, lo, hi);
    return pk2(fmaxf(lo, 0.0f), fmaxf(hi, 0.0f));
}

__device__ __forceinline__ float softplusf(float x) {
    return x > 20.0f ? x : __logf(1.0f + __expf(x));
}
__device__ __forceinline__ float sigmoidf(float x) {
    return __fdividef(1.0f, 1.0f + __expf(-x));
}
__device__ __forceinline__ float clamp1(float x) {
    return fminf(fmaxf(x, -1.0f), 1.0f);
}

__global__ __launch_bounds__(256) void nerf_render_kernel(
    const float* __restrict__ rays_o,
    const float* __restrict__ rays_d,
    const float* __restrict__ W1,      // [3,64]
    const float* __restrict__ b1,      // [64]
    const float* __restrict__ w_sigma, // [64,1]
    const float* __restrict__ b_sigma, // [1]
    const float* __restrict__ W_rgb,   // [64,3]
    const float* __restrict__ b_rgb,   // [3]
    float* __restrict__ out)           // [N_RAYS,3]
{
    // Duplicated-weight rows, 64B per hidden unit j:
    // [0]={W1x,W1x} [1]={W1y,W1y} [2]={W1z,W1z} [3]={b1,b1}
    // [4]={ws,ws}   [5]={wr,wr}   [6]={wg,wg}   [7]={wb,wb}
    __shared__ u64   sWd[64][8];
    __shared__ float sbias[4];             // b_sigma, b_rgb[0..2]
    __shared__ float zc[WARPS_PB][64];     // coarse z
    __shared__ float cdfs[WARPS_PB][64];   // cdf C[0..62]
    __shared__ float nz[WARPS_PB][64];     // new_z (sorted)
    __shared__ float zall[WARPS_PB][128];

    const int tid = threadIdx.x;
    if (tid < 64) {
        int j = tid;
        float ax = W1[j], ay = W1[64 + j], az = W1[128 + j], aw = b1[j];
        float ws = w_sigma[j], wr = W_rgb[3 * j], wg = W_rgb[3 * j + 1], wb = W_rgb[3 * j + 2];
        sWd[j][0] = pk2(ax, ax);
        sWd[j][1] = pk2(ay, ay);
        sWd[j][2] = pk2(az, az);
        sWd[j][3] = pk2(aw, aw);
        sWd[j][4] = pk2(ws, ws);
        sWd[j][5] = pk2(wr, wr);
        sWd[j][6] = pk2(wg, wg);
        sWd[j][7] = pk2(wb, wb);
    }
    if (tid == 64) {
        sbias[0] = b_sigma[0];
        sbias[1] = b_rgb[0];
        sbias[2] = b_rgb[1];
        sbias[3] = b_rgb[2];
    }
    __syncthreads();

    const int w    = tid >> 5;
    const int lane = tid & 31;
    const int ray  = blockIdx.x * WARPS_PB + w;

    // ---- ray setup (redundant across lanes) ----
    float ox = rays_o[3 * ray + 0], oy = rays_o[3 * ray + 1], oz = rays_o[3 * ray + 2];
    float dx = rays_d[3 * ray + 0], dy = rays_d[3 * ray + 1], dz = rays_d[3 * ray + 2];
    float inv = rsqrtf(dx * dx + dy * dy + dz * dz);
    dx *= inv; dy *= inv; dz *= inv;

    float t0x = (-1.0f - ox) / (dx + 1e-15f), t1x = (1.0f - ox) / (dx + 1e-15f);
    float t0y = (-1.0f - oy) / (dy + 1e-15f), t1y = (1.0f - oy) / (dy + 1e-15f);
    float t0z = (-1.0f - oz) / (dz + 1e-15f), t1z = (1.0f - oz) / (dz + 1e-15f);
    float lox = fminf(t0x, t1x), hix = fmaxf(t0x, t1x);
    float loy = fminf(t0y, t1y), hiy = fmaxf(t0y, t1y);
    float loz = fminf(t0z, t1z), hiz = fmaxf(t0z, t1z);
    float near = fmaxf(lox, fmaxf(loy, loz));
    float far  = fminf(hix, fminf(hiy, hiz));
    if (far < near) { near = 1e9f; far = 1e9f; }
    near = fmaxf(near, 0.05f);
    float span = far - near;
    float sample_dist = span * (1.0f / 64.0f);
    float dcoarse = span * (1.0f / 63.0f);   // uniform coarse spacing

    // ---- coarse samples: lane owns t = 2*lane, 2*lane+1 ----
    int tc0 = 2 * lane;
    float z0 = near + span * ((float)tc0       * (1.0f / 63.0f));
    float z1 = near + span * ((float)(tc0 + 1) * (1.0f / 63.0f));
    zc[w][tc0]     = z0;
    zc[w][tc0 + 1] = z1;

    u64 pxp = pk2(clamp1(ox + dx * z0), clamp1(ox + dx * z1));
    u64 pyp = pk2(clamp1(oy + dy * z0), clamp1(oy + dy * z1));
    u64 pzp = pk2(clamp1(oz + dz * z0), clamp1(oz + dz * z1));
    u64 sacc = pk2(sbias[0], sbias[0]);
    #pragma unroll 8
    for (int j = 0; j < 64; j++) {
        const ulonglong2* pw = reinterpret_cast<const ulonglong2*>(sWd[j]);
        ulonglong2 qa = pw[0];   // {ax,ax},{ay,ay}
        ulonglong2 qb = pw[1];   // {az,az},{aw,aw}
        u64 wsd = sWd[j][4];
        u64 hp = ffma2(pzp, qb.x, qb.y);
        hp = ffma2(pyp, qa.y, hp);
        hp = ffma2(pxp, qa.x, hp);
        hp = relu2(hp);
        sacc = ffma2(hp, wsd, sacc);
    }
    float s0, s1;
    upk2(sacc, s0, s1);
    float sig0 = softplusf(s0);
    float sig1 = softplusf(s1);

    // ---- coarse composite via warp product-scan ----
    float d0 = dcoarse;
    float d1 = (lane == 31) ? sample_dist : dcoarse;
    float q0 = __expf(-d0 * sig0) + 1e-15f;
    float q1 = __expf(-d1 * sig1) + 1e-15f;
    float a0 = 1.0f - (q0 - 1e-15f);
    float a1 = 1.0f - (q1 - 1e-15f);

    float incl = q0 * q1;
    #pragma unroll
    for (int o = 1; o < 32; o <<= 1) {
        float t = __shfl_up_sync(FULLMASK, incl, o);
        if (lane >= o) incl *= t;
    }
    float Texcl = __shfl_up_sync(FULLMASK, incl, 1);
    if (lane == 0) Texcl = 1.0f;
    float w0 = a0 * Texcl;
    float w1 = a1 * Texcl * q0;

    // ---- CDF via warp add-scan ----
    float v0 = (lane > 0)  ? (w0 + 1e-5f) : 0.0f;
    float v1 = (lane < 31) ? (w1 + 1e-5f) : 0.0f;
    float lsum = v0 + v1;
    float sincl = lsum;
    #pragma unroll
    for (int o = 1; o < 32; o <<= 1) {
        float t = __shfl_up_sync(FULLMASK, sincl, o);
        if (lane >= o) sincl += t;
    }
    float sexcl = __shfl_up_sync(FULLMASK, sincl, 1);
    if (lane == 0) sexcl = 0.0f;
    float S = __shfl_sync(FULLMASK, sincl, 31);
    float invS = __fdividef(1.0f, S);
    cdfs[w][tc0]     = (sexcl + v0) * invS;
    cdfs[w][tc0 + 1] = (sexcl + lsum) * invS;
    __syncwarp();

    // ---- inverse-CDF sampling ----
    #pragma unroll
    for (int p = 0; p < 2; p++) {
        int k = tc0 + p;
        float u = (float)(2 * k + 1) * (1.0f / 128.0f);
        int lo = 0, hi = 63;   // first idx in [0,63) with C[idx] > u
        while (lo < hi) {
            int m = (lo + hi) >> 1;
            if (cdfs[w][m] > u) hi = m; else lo = m + 1;
        }
        int ind = lo;
        int below = ind - 1;
        int above = (ind > 62) ? 62 : ind;
        float cb = cdfs[w][below], ca = cdfs[w][above];
        float bb = 0.5f * (zc[w][below] + zc[w][below + 1]);
        float ba = 0.5f * (zc[w][above] + zc[w][above + 1]);
        float denom = ca - cb;
        if (denom < 1e-5f) denom = 1.0f;
        nz[w][k] = bb + (u - cb) / denom * (ba - bb);
    }
    __syncwarp();

    // ---- merge sorted zc[64] + nz[64] -> zall[128] ----
    #pragma unroll
    for (int p = 0; p < 2; p++) {
        int t = tc0 + p;
        float v = zc[w][t];
        int lo = 0, hi = 64;           // count nz < v
        while (lo < hi) { int m = (lo + hi) >> 1; if (nz[w][m] < v) lo = m + 1; else hi = m; }
        zall[w][t + lo] = v;
        float v2 = nz[w][t];
        int lo2 = 0, hi2 = 64;         // count zc <= v2
        while (lo2 < hi2) { int m = (lo2 + hi2) >> 1; if (zc[w][m] <= v2) lo2 = m + 1; else hi2 = m; }
        zall[w][t + lo2] = v2;
    }
    __syncwarp();

    // ---- fine MLP: lane owns t = 4*lane .. 4*lane+3; 2 packed pairs ----
    float4 z4 = *reinterpret_cast<const float4*>(&zall[w][4 * lane]);
    float znext = (lane < 31) ? zall[w][4 * lane + 4] : 0.0f;
    float zr[4] = {z4.x, z4.y, z4.z, z4.w};

    u64 Px[2], Py[2], Pz[2];
    #pragma unroll
    for (int p = 0; p < 2; p++) {
        float za = zr[2 * p], zb = zr[2 * p + 1];
        Px[p] = pk2(clamp1(ox + dx * za), clamp1(ox + dx * zb));
        Py[p] = pk2(clamp1(oy + dy * za), clamp1(oy + dy * zb));
        Pz[p] = pk2(clamp1(oz + dz * za), clamp1(oz + dz * zb));
    }
    u64 As[2], Ar[2], Ag[2], Ab[2];
    As[0] = As[1] = pk2(sbias[0], sbias[0]);
    Ar[0] = Ar[1] = pk2(sbias[1], sbias[1]);
    Ag[0] = Ag[1] = pk2(sbias[2], sbias[2]);
    Ab[0] = Ab[1] = pk2(sbias[3], sbias[3]);

    #pragma unroll 4
    for (int j = 0; j < 64; j++) {
        const ulonglong2* pw = reinterpret_cast<const ulonglong2*>(sWd[j]);
        ulonglong2 qa = pw[0];   // {ax},{ay}
        ulonglong2 qb = pw[1];   // {az},{aw}
        ulonglong2 qc = pw[2];   // {ws},{wr}
        ulonglong2 qd = pw[3];   // {wg},{wb}
        #pragma unroll
        for (int p = 0; p < 2; p++) {
            u64 hp = ffma2(Pz[p], qb.x, qb.y);
            hp = ffma2(Py[p], qa.y, hp);
            hp = ffma2(Px[p], qa.x, hp);
            hp = relu2(hp);
            As[p] = ffma2(hp, qc.x, As[p]);
            Ar[p] = ffma2(hp, qc.y, Ar[p]);
            Ag[p] = ffma2(hp, qd.x, Ag[p]);
            Ab[p] = ffma2(hp, qd.y, Ab[p]);
        }
    }

    float fs[4], fr[4], fg[4], fb[4];
    upk2(As[0], fs[0], fs[1]); upk2(As[1], fs[2], fs[3]);
    upk2(Ar[0], fr[0], fr[1]); upk2(Ar[1], fr[2], fr[3]);
    upk2(Ag[0], fg[0], fg[1]); upk2(Ag[1], fg[2], fg[3]);
    upk2(Ab[0], fb[0], fb[1]); upk2(Ab[1], fb[2], fb[3]);

    float sg[4], qr[4], al[4], dd[4];
    dd[0] = z4.y - z4.x;
    dd[1] = z4.z - z4.y;
    dd[2] = z4.w - z4.z;
    dd[3] = (lane < 31) ? (znext - z4.w) : sample_dist;
    #pragma unroll
    for (int p = 0; p < 4; p++) {
        sg[p] = softplusf(fs[p]);
        fr[p] = sigmoidf(fr[p]);
        fg[p] = sigmoidf(fg[p]);
        fb[p] = sigmoidf(fb[p]);
        qr[p] = __expf(-dd[p] * sg[p]) + 1e-15f;
        al[p] = 1.0f - (qr[p] - 1e-15f);
    }

    // ---- fine composite: warp product-scan of transmittance ----
    float fincl = (qr[0] * qr[1]) * (qr[2] * qr[3]);
    #pragma unroll
    for (int o = 1; o < 32; o <<= 1) {
        float t = __shfl_up_sync(FULLMASK, fincl, o);
        if (lane >= o) fincl *= t;
    }
    float T0 = __shfl_up_sync(FULLMASK, fincl, 1);
    if (lane == 0) T0 = 1.0f;
    float T1 = T0 * qr[0];
    float T2 = T1 * qr[1];
    float T3 = T2 * qr[2];

    float wt0 = al[0] * T0, wt1 = al[1] * T1, wt2 = al[2] * T2, wt3 = al[3] * T3;
    float wsum = (wt0 + wt1) + (wt2 + wt3);
    float i0 = fmaf(wt0, fr[0], fmaf(wt1, fr[1], fmaf(wt2, fr[2], wt3 * fr[3])));
    float i1 = fmaf(wt0, fg[0], fmaf(wt1, fg[1], fmaf(wt2, fg[2], wt3 * fg[3])));
    float i2 = fmaf(wt0, fb[0], fmaf(wt1, fb[1], fmaf(wt2, fb[2], wt3 * fb[3])));

    #pragma unroll
    for (int o = 16; o > 0; o >>= 1) {
        i0   += __shfl_xor_sync(FULLMASK, i0, o);
        i1   += __shfl_xor_sync(FULLMASK, i1, o);
        i2   += __shfl_xor_sync(FULLMASK, i2, o);
        wsum += __shfl_xor_sync(FULLMASK, wsum, o);
    }

    if (lane == 0) {
        float bg = 1.0f - wsum;
        out[3 * ray + 0] = i0 + bg;
        out[3 * ray + 1] = i1 + bg;
        out[3 * ray + 2] = i2 + bg;
    }
}

extern "C" void kernel_launch(void* const* d_in, const int* in_sizes, int n_in,
                              void* d_out, int out_size) {
    const float* rays_o  = (const float*)d_in[0];
    const float* rays_d  = (const float*)d_in[1];
    const float* W1      = (const float*)d_in[2];
    const float* b1      = (const float*)d_in[3];
    const float* w_sigma = (const float*)d_in[4];
    const float* b_sigma = (const float*)d_in[5];
    const float* W_rgb   = (const float*)d_in[6];
    const float* b_rgb   = (const float*)d_in[7];
    float* out = (float*)d_out;

    nerf_render_kernel<<<BLOCKS, 256>>>(rays_o, rays_d, W1, b1, w_sigma, b_sigma,
                                        W_rgb, b_rgb, out);
}

// round 4
// speedup vs baseline: 1.1124x; 1.1124x over previous
#include <cuda_runtime.h>
#include <cuda_bf16.h>

// NeRF renderer: 16384 rays, 64 coarse + 64 importance samples, 3->64->{1,3} MLP.
// One warp per ray. FFMA2 packed across HIDDEN-UNIT pairs (point replicated in
// both halves) so weights load in natural pair-interleaved layout (32B/unit,
// same LDS bytes as scalar version, half the math issues).

#define N_RAYS     16384
#define WARPS_PB   4
#define BLOCKS     (N_RAYS / WARPS_PB)
#define FULLMASK   0xffffffffu

typedef unsigned long long u64;

__device__ __forceinline__ u64 pk2(float lo, float hi) {
    u64 r;
    asm("mov.b64 %0, {%1, %2};" : "=l"(r) : "f"(lo), "f"(hi));
    return r;
}
__device__ __forceinline__ void upk2(u64 v, float& lo, float& hi) {
    asm("mov.b64 {%0, %1}, %2;" : "=f"(lo), "=f"(hi) : "l"(v));
}
__device__ __forceinline__ u64 ffma2(u64 a, u64 b, u64 c) {
    u64 d;
    asm("fma.rn.f32x2 %0, %1, %2, %3;" : "=l"(d) : "l"(a), "l"(b), "l"(c));
    return d;
}
__device__ __forceinline__ u64 relu2(u64 x) {
    float lo, hi;
    upk2(x, lo, hi);
    return pk2(fmaxf(lo, 0.0f), fmaxf(hi, 0.0f));
}
__device__ __forceinline__ float hsum2(u64 x) {
    float lo, hi;
    upk2(x, lo, hi);
    return lo + hi;
}

__device__ __forceinline__ float softplusf(float x) {
    return x > 20.0f ? x : __logf(1.0f + __expf(x));
}
__device__ __forceinline__ float sigmoidf(float x) {
    return __fdividef(1.0f, 1.0f + __expf(-x));
}
__device__ __forceinline__ float clamp1(float x) {
    return fminf(fmaxf(x, -1.0f), 1.0f);
}

__global__ __launch_bounds__(128) void nerf_render_kernel(
    const float* __restrict__ rays_o,
    const float* __restrict__ rays_d,
    const float* __restrict__ W1,      // [3,64]
    const float* __restrict__ b1,      // [64]
    const float* __restrict__ w_sigma, // [64,1]
    const float* __restrict__ b_sigma, // [1]
    const float* __restrict__ W_rgb,   // [64,3]
    const float* __restrict__ b_rgb,   // [3]
    float* __restrict__ out)           // [N_RAYS,3]
{
    // Unit-pair weight blocks, 64B per pair j2 (units 2*j2, 2*j2+1):
    // [0..1]={ax_e,ax_o} [2..3]={ay_e,ay_o} [4..5]={az_e,az_o} [6..7]={b_e,b_o}
    // [8..9]={ws}        [10..11]={wr}      [12..13]={wg}      [14..15]={wb}
    __shared__ float sWp[32][16];
    __shared__ float sbias[4];             // b_sigma, b_rgb[0..2]
    __shared__ float zc[WARPS_PB][64];     // coarse z
    __shared__ float cdfs[WARPS_PB][64];   // cdf C[0..62]
    __shared__ float nz[WARPS_PB][64];     // new_z (sorted)
    __shared__ float zall[WARPS_PB][128];

    const int tid = threadIdx.x;
    if (tid < 32) {
        int j0 = 2 * tid, j1 = j0 + 1;
        sWp[tid][0]  = W1[j0];         sWp[tid][1]  = W1[j1];
        sWp[tid][2]  = W1[64 + j0];    sWp[tid][3]  = W1[64 + j1];
        sWp[tid][4]  = W1[128 + j0];   sWp[tid][5]  = W1[128 + j1];
        sWp[tid][6]  = b1[j0];         sWp[tid][7]  = b1[j1];
        sWp[tid][8]  = w_sigma[j0];    sWp[tid][9]  = w_sigma[j1];
        sWp[tid][10] = W_rgb[3 * j0];      sWp[tid][11] = W_rgb[3 * j1];
        sWp[tid][12] = W_rgb[3 * j0 + 1];  sWp[tid][13] = W_rgb[3 * j1 + 1];
        sWp[tid][14] = W_rgb[3 * j0 + 2];  sWp[tid][15] = W_rgb[3 * j1 + 2];
    }
    if (tid == 32) {
        sbias[0] = b_sigma[0];
        sbias[1] = b_rgb[0];
        sbias[2] = b_rgb[1];
        sbias[3] = b_rgb[2];
    }
    __syncthreads();

    const int w    = tid >> 5;
    const int lane = tid & 31;
    const int ray  = blockIdx.x * WARPS_PB + w;

    // ---- ray setup (redundant across lanes) ----
    float ox = rays_o[3 * ray + 0], oy = rays_o[3 * ray + 1], oz = rays_o[3 * ray + 2];
    float dx = rays_d[3 * ray + 0], dy = rays_d[3 * ray + 1], dz = rays_d[3 * ray + 2];
    float inv = rsqrtf(dx * dx + dy * dy + dz * dz);
    dx *= inv; dy *= inv; dz *= inv;

    float t0x = (-1.0f - ox) / (dx + 1e-15f), t1x = (1.0f - ox) / (dx + 1e-15f);
    float t0y = (-1.0f - oy) / (dy + 1e-15f), t1y = (1.0f - oy) / (dy + 1e-15f);
    float t0z = (-1.0f - oz) / (dz + 1e-15f), t1z = (1.0f - oz) / (dz + 1e-15f);
    float lox = fminf(t0x, t1x), hix = fmaxf(t0x, t1x);
    float loy = fminf(t0y, t1y), hiy = fmaxf(t0y, t1y);
    float loz = fminf(t0z, t1z), hiz = fmaxf(t0z, t1z);
    float near = fmaxf(lox, fmaxf(loy, loz));
    float far  = fminf(hix, fminf(hiy, hiz));
    if (far < near) { near = 1e9f; far = 1e9f; }
    near = fmaxf(near, 0.05f);
    float span = far - near;
    float sample_dist = span * (1.0f / 64.0f);
    float dcoarse = span * (1.0f / 63.0f);   // uniform coarse spacing

    // ---- coarse samples: lane owns t = 2*lane, 2*lane+1 ----
    int tc0 = 2 * lane;
    float z0 = near + span * ((float)tc0       * (1.0f / 63.0f));
    float z1 = near + span * ((float)(tc0 + 1) * (1.0f / 63.0f));
    zc[w][tc0]     = z0;
    zc[w][tc0 + 1] = z1;

    // packed points: coordinate replicated in both halves
    u64 cx0 = pk2(clamp1(ox + dx * z0), clamp1(ox + dx * z0));
    u64 cy0 = pk2(clamp1(oy + dy * z0), clamp1(oy + dy * z0));
    u64 cz0 = pk2(clamp1(oz + dz * z0), clamp1(oz + dz * z0));
    u64 cx1 = pk2(clamp1(ox + dx * z1), clamp1(ox + dx * z1));
    u64 cy1 = pk2(clamp1(oy + dy * z1), clamp1(oy + dy * z1));
    u64 cz1 = pk2(clamp1(oz + dz * z1), clamp1(oz + dz * z1));
    u64 sacc0 = pk2(sbias[0], 0.0f);
    u64 sacc1 = pk2(sbias[0], 0.0f);
    #pragma unroll 8
    for (int j2 = 0; j2 < 32; j2++) {
        const ulonglong2* pw = reinterpret_cast<const ulonglong2*>(sWp[j2]);
        ulonglong2 qa = pw[0];   // ax2, ay2
        ulonglong2 qb = pw[1];   // az2, b2
        u64 ws2 = reinterpret_cast<const u64*>(sWp[j2])[4];
        u64 h0 = ffma2(cz0, qb.x, qb.y);
        h0 = ffma2(cy0, qa.y, h0);
        h0 = ffma2(cx0, qa.x, h0);
        h0 = relu2(h0);
        sacc0 = ffma2(h0, ws2, sacc0);
        u64 h1 = ffma2(cz1, qb.x, qb.y);
        h1 = ffma2(cy1, qa.y, h1);
        h1 = ffma2(cx1, qa.x, h1);
        h1 = relu2(h1);
        sacc1 = ffma2(h1, ws2, sacc1);
    }
    float sig0 = softplusf(hsum2(sacc0));
    float sig1 = softplusf(hsum2(sacc1));

    // ---- coarse composite via warp product-scan ----
    float d0 = dcoarse;
    float d1 = (lane == 31) ? sample_dist : dcoarse;
    float q0 = __expf(-d0 * sig0) + 1e-15f;
    float q1 = __expf(-d1 * sig1) + 1e-15f;
    float a0 = 1.0f - (q0 - 1e-15f);
    float a1 = 1.0f - (q1 - 1e-15f);

    float incl = q0 * q1;
    #pragma unroll
    for (int o = 1; o < 32; o <<= 1) {
        float t = __shfl_up_sync(FULLMASK, incl, o);
        if (lane >= o) incl *= t;
    }
    float Texcl = __shfl_up_sync(FULLMASK, incl, 1);
    if (lane == 0) Texcl = 1.0f;
    float w0 = a0 * Texcl;
    float w1 = a1 * Texcl * q0;

    // ---- CDF via warp add-scan ----
    float v0 = (lane > 0)  ? (w0 + 1e-5f) : 0.0f;
    float v1 = (lane < 31) ? (w1 + 1e-5f) : 0.0f;
    float lsum = v0 + v1;
    float sincl = lsum;
    #pragma unroll
    for (int o = 1; o < 32; o <<= 1) {
        float t = __shfl_up_sync(FULLMASK, sincl, o);
        if (lane >= o) sincl += t;
    }
    float sexcl = __shfl_up_sync(FULLMASK, sincl, 1);
    if (lane == 0) sexcl = 0.0f;
    float S = __shfl_sync(FULLMASK, sincl, 31);
    float invS = __fdividef(1.0f, S);
    cdfs[w][tc0]     = (sexcl + v0) * invS;
    cdfs[w][tc0 + 1] = (sexcl + lsum) * invS;
    __syncwarp();

    // ---- inverse-CDF sampling ----
    #pragma unroll
    for (int p = 0; p < 2; p++) {
        int k = tc0 + p;
        float u = (float)(2 * k + 1) * (1.0f / 128.0f);
        int lo = 0, hi = 63;   // first idx in [0,63) with C[idx] > u
        while (lo < hi) {
            int m = (lo + hi) >> 1;
            if (cdfs[w][m] > u) hi = m; else lo = m + 1;
        }
        int ind = lo;
        int below = ind - 1;
        int above = (ind > 62) ? 62 : ind;
        float cb = cdfs[w][below], ca = cdfs[w][above];
        float bb = 0.5f * (zc[w][below] + zc[w][below + 1]);
        float ba = 0.5f * (zc[w][above] + zc[w][above + 1]);
        float denom = ca - cb;
        if (denom < 1e-5f) denom = 1.0f;
        nz[w][k] = bb + (u - cb) / denom * (ba - bb);
    }
    __syncwarp();

    // ---- merge sorted zc[64] + nz[64] -> zall[128] ----
    #pragma unroll
    for (int p = 0; p < 2; p++) {
        int t = tc0 + p;
        float v = zc[w][t];
        int lo = 0, hi = 64;           // count nz < v
        while (lo < hi) { int m = (lo + hi) >> 1; if (nz[w][m] < v) lo = m + 1; else hi = m; }
        zall[w][t + lo] = v;
        float v2 = nz[w][t];
        int lo2 = 0, hi2 = 64;         // count zc <= v2
        while (lo2 < hi2) { int m = (lo2 + hi2) >> 1; if (zc[w][m] <= v2) lo2 = m + 1; else hi2 = m; }
        zall[w][t + lo2] = v2;
    }
    __syncwarp();

    // ---- fine MLP: lane owns t = 4*lane .. 4*lane+3 ----
    float4 z4 = *reinterpret_cast<const float4*>(&zall[w][4 * lane]);
    float znext = (lane < 31) ? zall[w][4 * lane + 4] : 0.0f;
    float zr[4] = {z4.x, z4.y, z4.z, z4.w};

    u64 Px[4], Py[4], Pz[4];
    u64 As[4], Ar[4], Ag[4], Ab[4];
    #pragma unroll
    for (int p = 0; p < 4; p++) {
        float px = clamp1(ox + dx * zr[p]);
        float py = clamp1(oy + dy * zr[p]);
        float pz = clamp1(oz + dz * zr[p]);
        Px[p] = pk2(px, px);
        Py[p] = pk2(py, py);
        Pz[p] = pk2(pz, pz);
        As[p] = pk2(sbias[0], 0.0f);
        Ar[p] = pk2(sbias[1], 0.0f);
        Ag[p] = pk2(sbias[2], 0.0f);
        Ab[p] = pk2(sbias[3], 0.0f);
    }

    #pragma unroll 4
    for (int j2 = 0; j2 < 32; j2++) {
        const ulonglong2* pw = reinterpret_cast<const ulonglong2*>(sWp[j2]);
        ulonglong2 qa = pw[0];   // ax2, ay2
        ulonglong2 qb = pw[1];   // az2, b2
        ulonglong2 qc = pw[2];   // ws2, wr2
        ulonglong2 qd = pw[3];   // wg2, wb2
        #pragma unroll
        for (int p = 0; p < 4; p++) {
            u64 h = ffma2(Pz[p], qb.x, qb.y);
            h = ffma2(Py[p], qa.y, h);
            h = ffma2(Px[p], qa.x, h);
            h = relu2(h);
            As[p] = ffma2(h, qc.x, As[p]);
            Ar[p] = ffma2(h, qc.y, Ar[p]);
            Ag[p] = ffma2(h, qd.x, Ag[p]);
            Ab[p] = ffma2(h, qd.y, Ab[p]);
        }
    }

    float fs[4], fr[4], fg[4], fb[4];
    #pragma unroll
    for (int p = 0; p < 4; p++) {
        fs[p] = hsum2(As[p]);
        fr[p] = hsum2(Ar[p]);
        fg[p] = hsum2(Ag[p]);
        fb[p] = hsum2(Ab[p]);
    }

    float sg[4], qr[4], al[4], dd[4];
    dd[0] = z4.y - z4.x;
    dd[1] = z4.z - z4.y;
    dd[2] = z4.w - z4.z;
    dd[3] = (lane < 31) ? (znext - z4.w) : sample_dist;
    #pragma unroll
    for (int p = 0; p < 4; p++) {
        sg[p] = softplusf(fs[p]);
        fr[p] = sigmoidf(fr[p]);
        fg[p] = sigmoidf(fg[p]);
        fb[p] = sigmoidf(fb[p]);
        qr[p] = __expf(-dd[p] * sg[p]) + 1e-15f;
        al[p] = 1.0f - (qr[p] - 1e-15f);
    }

    // ---- fine composite: warp product-scan of transmittance ----
    float fincl = (qr[0] * qr[1]) * (qr[2] * qr[3]);
    #pragma unroll
    for (int o = 1; o < 32; o <<= 1) {
        float t = __shfl_up_sync(FULLMASK, fincl, o);
        if (lane >= o) fincl *= t;
    }
    float T0 = __shfl_up_sync(FULLMASK, fincl, 1);
    if (lane == 0) T0 = 1.0f;
    float T1 = T0 * qr[0];
    float T2 = T1 * qr[1];
    float T3 = T2 * qr[2];

    float wt0 = al[0] * T0, wt1 = al[1] * T1, wt2 = al[2] * T2, wt3 = al[3] * T3;
    float wsum = (wt0 + wt1) + (wt2 + wt3);
    float i0 = fmaf(wt0, fr[0], fmaf(wt1, fr[1], fmaf(wt2, fr[2], wt3 * fr[3])));
    float i1 = fmaf(wt0, fg[0], fmaf(wt1, fg[1], fmaf(wt2, fg[2], wt3 * fg[3])));
    float i2 = fmaf(wt0, fb[0], fmaf(wt1, fb[1], fmaf(wt2, fb[2], wt3 * fb[3])));

    #pragma unroll
    for (int o = 16; o > 0; o >>= 1) {
        i0   += __shfl_xor_sync(FULLMASK, i0, o);
        i1   += __shfl_xor_sync(FULLMASK, i1, o);
        i2   += __shfl_xor_sync(FULLMASK, i2, o);
        wsum += __shfl_xor_sync(FULLMASK, wsum, o);
    }

    if (lane == 0) {
        float bg = 1.0f - wsum;
        out[3 * ray + 0] = i0 + bg;
        out[3 * ray + 1] = i1 + bg;
        out[3 * ray + 2] = i2 + bg;
    }
}

extern "C" void kernel_launch(void* const* d_in, const int* in_sizes, int n_in,
                              void* d_out, int out_size) {
    const float* rays_o  = (const float*)d_in[0];
    const float* rays_d  = (const float*)d_in[1];
    const float* W1      = (const float*)d_in[2];
    const float* b1      = (const float*)d_in[3];
    const float* w_sigma = (const float*)d_in[4];
    const float* b_sigma = (const float*)d_in[5];
    const float* W_rgb   = (const float*)d_in[6];
    const float* b_rgb   = (const float*)d_in[7];
    float* out = (float*)d_out;

    nerf_render_kernel<<<BLOCKS, 128>>>(rays_o, rays_d, W1, b1, w_sigma, b_sigma,
                                        W_rgb, b_rgb, out);
}

// round 5
// speedup vs baseline: 1.3901x; 1.2496x over previous
#include <cuda_runtime.h>
#include <cuda_bf16.h>

// NeRF renderer: 16384 rays, 64 coarse + 64 importance samples, 3->64->{1,3} MLP.
// One warp per ray. Affine fold: h_j(z) = g_j*z + c_j with per-ray (g,c)
// precomputed once per warp (clip is a no-op for hit rays; miss rays exactly
// handled by (o,d)->(clip(o+d*1e9), 0)). FFMA2 packed across hidden-unit pairs.

#define N_RAYS     16384
#define WARPS_PB   4
#define BLOCKS     (N_RAYS / WARPS_PB)
#define FULLMASK   0xffffffffu

typedef unsigned long long u64;

__device__ __forceinline__ u64 pk2(float lo, float hi) {
    u64 r;
    asm("mov.b64 %0, {%1, %2};" : "=l"(r) : "f"(lo), "f"(hi));
    return r;
}
__device__ __forceinline__ void upk2(u64 v, float& lo, float& hi) {
    asm("mov.b64 {%0, %1}, %2;" : "=f"(lo), "=f"(hi) : "l"(v));
}
__device__ __forceinline__ u64 ffma2(u64 a, u64 b, u64 c) {
    u64 d;
    asm("fma.rn.f32x2 %0, %1, %2, %3;" : "=l"(d) : "l"(a), "l"(b), "l"(c));
    return d;
}
__device__ __forceinline__ u64 relu2(u64 x) {
    float lo, hi;
    upk2(x, lo, hi);
    return pk2(fmaxf(lo, 0.0f), fmaxf(hi, 0.0f));
}
__device__ __forceinline__ float hsum2(u64 x) {
    float lo, hi;
    upk2(x, lo, hi);
    return lo + hi;
}

__device__ __forceinline__ float softplusf(float x) {
    return x > 20.0f ? x : __logf(1.0f + __expf(x));
}
__device__ __forceinline__ float sigmoidf(float x) {
    return __fdividef(1.0f, 1.0f + __expf(-x));
}
__device__ __forceinline__ float clamp1(float x) {
    return fminf(fmaxf(x, -1.0f), 1.0f);
}

__global__ __launch_bounds__(128, 8) void nerf_render_kernel(
    const float* __restrict__ rays_o,
    const float* __restrict__ rays_d,
    const float* __restrict__ W1,      // [3,64]
    const float* __restrict__ b1,      // [64]
    const float* __restrict__ w_sigma, // [64,1]
    const float* __restrict__ b_sigma, // [1]
    const float* __restrict__ W_rgb,   // [64,3]
    const float* __restrict__ b_rgb,   // [3]
    float* __restrict__ out)           // [N_RAYS,3]
{
    // Output weights, pair-interleaved: [ws_e,ws_o, wr_e,wr_o, wg_e,wg_o, wb_e,wb_o]
    __shared__ __align__(16) float sOut[32][8];
    __shared__ float sbias[4];             // b_sigma, b_rgb[0..2]
    // Per-ray folded input layer: gc[w][j2] = { {g_e,g_o}, {c_e,c_o} }
    __shared__ ulonglong2 gc[WARPS_PB][32];
    __shared__ float zc[WARPS_PB][64];     // coarse z
    __shared__ float cdfs[WARPS_PB][64];   // cdf C[0..62]
    __shared__ float nz[WARPS_PB][64];     // new_z (sorted)
    __shared__ float zall[WARPS_PB][128];

    const int tid = threadIdx.x;
    if (tid < 32) {
        int j0 = 2 * tid, j1 = j0 + 1;
        sOut[tid][0] = w_sigma[j0];        sOut[tid][1] = w_sigma[j1];
        sOut[tid][2] = W_rgb[3 * j0];      sOut[tid][3] = W_rgb[3 * j1];
        sOut[tid][4] = W_rgb[3 * j0 + 1];  sOut[tid][5] = W_rgb[3 * j1 + 1];
        sOut[tid][6] = W_rgb[3 * j0 + 2];  sOut[tid][7] = W_rgb[3 * j1 + 2];
    }
    if (tid == 32) {
        sbias[0] = b_sigma[0];
        sbias[1] = b_rgb[0];
        sbias[2] = b_rgb[1];
        sbias[3] = b_rgb[2];
    }
    __syncthreads();

    const int w    = tid >> 5;
    const int lane = tid & 31;
    const int ray  = blockIdx.x * WARPS_PB + w;

    // ---- ray setup (redundant across lanes) ----
    float ox = rays_o[3 * ray + 0], oy = rays_o[3 * ray + 1], oz = rays_o[3 * ray + 2];
    float dx = rays_d[3 * ray + 0], dy = rays_d[3 * ray + 1], dz = rays_d[3 * ray + 2];
    float inv = rsqrtf(dx * dx + dy * dy + dz * dz);
    dx *= inv; dy *= inv; dz *= inv;

    float t0x = (-1.0f - ox) / (dx + 1e-15f), t1x = (1.0f - ox) / (dx + 1e-15f);
    float t0y = (-1.0f - oy) / (dy + 1e-15f), t1y = (1.0f - oy) / (dy + 1e-15f);
    float t0z = (-1.0f - oz) / (dz + 1e-15f), t1z = (1.0f - oz) / (dz + 1e-15f);
    float lox = fminf(t0x, t1x), hix = fmaxf(t0x, t1x);
    float loy = fminf(t0y, t1y), hiy = fmaxf(t0y, t1y);
    float loz = fminf(t0z, t1z), hiz = fmaxf(t0z, t1z);
    float near = fmaxf(lox, fmaxf(loy, loz));
    float far  = fminf(hix, fminf(hiy, hiz));
    bool miss = (far < near);
    if (miss) { near = 1e9f; far = 1e9f; }
    near = fmaxf(near, 0.05f);
    float span = far - near;
    float sample_dist = span * (1.0f / 64.0f);
    float dcoarse = span * (1.0f / 63.0f);

    if (miss) {
        // exact clamp semantics for miss rays: all samples land on the same
        // clipped point; fold with d=0 reproduces it for every z.
        ox = clamp1(ox + dx * 1e9f);
        oy = clamp1(oy + dy * 1e9f);
        oz = clamp1(oz + dz * 1e9f);
        dx = 0.0f; dy = 0.0f; dz = 0.0f;
    }

    // ---- per-ray folded input layer: lane computes its unit pair ----
    {
        const float2* W1v = reinterpret_cast<const float2*>(W1);
        float2 ax2 = W1v[lane];
        float2 ay2 = W1v[32 + lane];
        float2 az2 = W1v[64 + lane];
        float2 b2  = reinterpret_cast<const float2*>(b1)[lane];
        float ge = fmaf(ax2.x, dx, fmaf(ay2.x, dy, az2.x * dz));
        float go = fmaf(ax2.y, dx, fmaf(ay2.y, dy, az2.y * dz));
        float ce = fmaf(ax2.x, ox, fmaf(ay2.x, oy, fmaf(az2.x, oz, b2.x)));
        float co = fmaf(ax2.y, ox, fmaf(ay2.y, oy, fmaf(az2.y, oz, b2.y)));
        gc[w][lane] = make_ulonglong2(pk2(ge, go), pk2(ce, co));
    }
    __syncwarp();

    // ---- coarse samples: lane owns t = 2*lane, 2*lane+1 ----
    int tc0 = 2 * lane;
    float z0 = near + span * ((float)tc0       * (1.0f / 63.0f));
    float z1 = near + span * ((float)(tc0 + 1) * (1.0f / 63.0f));
    zc[w][tc0]     = z0;
    zc[w][tc0 + 1] = z1;

    u64 Zc0 = pk2(z0, z0);
    u64 Zc1 = pk2(z1, z1);
    u64 sacc0 = pk2(sbias[0], 0.0f);
    u64 sacc1 = pk2(sbias[0], 0.0f);
    #pragma unroll 8
    for (int j2 = 0; j2 < 32; j2++) {
        ulonglong2 gcv = gc[w][j2];
        u64 ws2 = *reinterpret_cast<const u64*>(&sOut[j2][0]);
        u64 h0 = relu2(ffma2(Zc0, gcv.x, gcv.y));
        sacc0 = ffma2(h0, ws2, sacc0);
        u64 h1 = relu2(ffma2(Zc1, gcv.x, gcv.y));
        sacc1 = ffma2(h1, ws2, sacc1);
    }
    float sig0 = softplusf(hsum2(sacc0));
    float sig1 = softplusf(hsum2(sacc1));

    // ---- coarse composite via warp product-scan ----
    float d0 = dcoarse;
    float d1 = (lane == 31) ? sample_dist : dcoarse;
    float q0 = __expf(-d0 * sig0) + 1e-15f;
    float q1 = __expf(-d1 * sig1) + 1e-15f;
    float a0 = 1.0f - (q0 - 1e-15f);
    float a1 = 1.0f - (q1 - 1e-15f);

    float incl = q0 * q1;
    #pragma unroll
    for (int o = 1; o < 32; o <<= 1) {
        float t = __shfl_up_sync(FULLMASK, incl, o);
        if (lane >= o) incl *= t;
    }
    float Texcl = __shfl_up_sync(FULLMASK, incl, 1);
    if (lane == 0) Texcl = 1.0f;
    float w0 = a0 * Texcl;
    float w1 = a1 * Texcl * q0;

    // ---- CDF via warp add-scan ----
    float v0 = (lane > 0)  ? (w0 + 1e-5f) : 0.0f;
    float v1 = (lane < 31) ? (w1 + 1e-5f) : 0.0f;
    float lsum = v0 + v1;
    float sincl = lsum;
    #pragma unroll
    for (int o = 1; o < 32; o <<= 1) {
        float t = __shfl_up_sync(FULLMASK, sincl, o);
        if (lane >= o) sincl += t;
    }
    float sexcl = __shfl_up_sync(FULLMASK, sincl, 1);
    if (lane == 0) sexcl = 0.0f;
    float S = __shfl_sync(FULLMASK, sincl, 31);
    float invS = __fdividef(1.0f, S);
    cdfs[w][tc0]     = (sexcl + v0) * invS;
    cdfs[w][tc0 + 1] = (sexcl + lsum) * invS;
    __syncwarp();

    // ---- inverse-CDF sampling ----
    #pragma unroll
    for (int p = 0; p < 2; p++) {
        int k = tc0 + p;
        float u = (float)(2 * k + 1) * (1.0f / 128.0f);
        int lo = 0, hi = 63;   // first idx in [0,63) with C[idx] > u
        while (lo < hi) {
            int m = (lo + hi) >> 1;
            if (cdfs[w][m] > u) hi = m; else lo = m + 1;
        }
        int ind = lo;
        int below = ind - 1;
        int above = (ind > 62) ? 62 : ind;
        float cb = cdfs[w][below], ca = cdfs[w][above];
        float bb = 0.5f * (zc[w][below] + zc[w][below + 1]);
        float ba = 0.5f * (zc[w][above] + zc[w][above + 1]);
        float denom = ca - cb;
        if (denom < 1e-5f) denom = 1.0f;
        nz[w][k] = bb + (u - cb) / denom * (ba - bb);
    }
    __syncwarp();

    // ---- merge sorted zc[64] + nz[64] -> zall[128] ----
    #pragma unroll
    for (int p = 0; p < 2; p++) {
        int t = tc0 + p;
        float v = zc[w][t];
        int lo = 0, hi = 64;           // count nz < v
        while (lo < hi) { int m = (lo + hi) >> 1; if (nz[w][m] < v) lo = m + 1; else hi = m; }
        zall[w][t + lo] = v;
        float v2 = nz[w][t];
        int lo2 = 0, hi2 = 64;         // count zc <= v2
        while (lo2 < hi2) { int m = (lo2 + hi2) >> 1; if (zc[w][m] <= v2) lo2 = m + 1; else hi2 = m; }
        zall[w][t + lo2] = v2;
    }
    __syncwarp();

    // ---- fine MLP: lane owns t = 4*lane .. 4*lane+3 ----
    float4 z4 = *reinterpret_cast<const float4*>(&zall[w][4 * lane]);
    float znext = (lane < 31) ? zall[w][4 * lane + 4] : 0.0f;

    u64 Zp[4];
    Zp[0] = pk2(z4.x, z4.x);
    Zp[1] = pk2(z4.y, z4.y);
    Zp[2] = pk2(z4.z, z4.z);
    Zp[3] = pk2(z4.w, z4.w);
    u64 As[4], Ar[4], Ag[4], Ab[4];
    #pragma unroll
    for (int p = 0; p < 4; p++) {
        As[p] = pk2(sbias[0], 0.0f);
        Ar[p] = pk2(sbias[1], 0.0f);
        Ag[p] = pk2(sbias[2], 0.0f);
        Ab[p] = pk2(sbias[3], 0.0f);
    }

    #pragma unroll 4
    for (int j2 = 0; j2 < 32; j2++) {
        ulonglong2 gcv = gc[w][j2];
        const ulonglong2* po = reinterpret_cast<const ulonglong2*>(sOut[j2]);
        ulonglong2 o1 = po[0];   // ws2, wr2
        ulonglong2 o2 = po[1];   // wg2, wb2
        #pragma unroll
        for (int p = 0; p < 4; p++) {
            u64 h = relu2(ffma2(Zp[p], gcv.x, gcv.y));
            As[p] = ffma2(h, o1.x, As[p]);
            Ar[p] = ffma2(h, o1.y, Ar[p]);
            Ag[p] = ffma2(h, o2.x, Ag[p]);
            Ab[p] = ffma2(h, o2.y, Ab[p]);
        }
    }

    float fs[4], fr[4], fg[4], fb[4];
    #pragma unroll
    for (int p = 0; p < 4; p++) {
        fs[p] = hsum2(As[p]);
        fr[p] = hsum2(Ar[p]);
        fg[p] = hsum2(Ag[p]);
        fb[p] = hsum2(Ab[p]);
    }

    float sg[4], qr[4], al[4], dd[4];
    dd[0] = z4.y - z4.x;
    dd[1] = z4.z - z4.y;
    dd[2] = z4.w - z4.z;
    dd[3] = (lane < 31) ? (znext - z4.w) : sample_dist;
    #pragma unroll
    for (int p = 0; p < 4; p++) {
        sg[p] = softplusf(fs[p]);
        fr[p] = sigmoidf(fr[p]);
        fg[p] = sigmoidf(fg[p]);
        fb[p] = sigmoidf(fb[p]);
        qr[p] = __expf(-dd[p] * sg[p]) + 1e-15f;
        al[p] = 1.0f - (qr[p] - 1e-15f);
    }

    // ---- fine composite: warp product-scan of transmittance ----
    float fincl = (qr[0] * qr[1]) * (qr[2] * qr[3]);
    #pragma unroll
    for (int o = 1; o < 32; o <<= 1) {
        float t = __shfl_up_sync(FULLMASK, fincl, o);
        if (lane >= o) fincl *= t;
    }
    float T0 = __shfl_up_sync(FULLMASK, fincl, 1);
    if (lane == 0) T0 = 1.0f;
    float T1 = T0 * qr[0];
    float T2 = T1 * qr[1];
    float T3 = T2 * qr[2];

    float wt0 = al[0] * T0, wt1 = al[1] * T1, wt2 = al[2] * T2, wt3 = al[3] * T3;
    float wsum = (wt0 + wt1) + (wt2 + wt3);
    float i0 = fmaf(wt0, fr[0], fmaf(wt1, fr[1], fmaf(wt2, fr[2], wt3 * fr[3])));
    float i1 = fmaf(wt0, fg[0], fmaf(wt1, fg[1], fmaf(wt2, fg[2], wt3 * fg[3])));
    float i2 = fmaf(wt0, fb[0], fmaf(wt1, fb[1], fmaf(wt2, fb[2], wt3 * fb[3])));

    #pragma unroll
    for (int o = 16; o > 0; o >>= 1) {
        i0   += __shfl_xor_sync(FULLMASK, i0, o);
        i1   += __shfl_xor_sync(FULLMASK, i1, o);
        i2   += __shfl_xor_sync(FULLMASK, i2, o);
        wsum += __shfl_xor_sync(FULLMASK, wsum, o);
    }

    if (lane == 0) {
        float bg = 1.0f - wsum;
        out[3 * ray + 0] = i0 + bg;
        out[3 * ray + 1] = i1 + bg;
        out[3 * ray + 2] = i2 + bg;
    }
}

extern "C" void kernel_launch(void* const* d_in, const int* in_sizes, int n_in,
                              void* d_out, int out_size) {
    const float* rays_o  = (const float*)d_in[0];
    const float* rays_d  = (const float*)d_in[1];
    const float* W1      = (const float*)d_in[2];
    const float* b1      = (const float*)d_in[3];
    const float* w_sigma = (const float*)d_in[4];
    const float* b_sigma = (const float*)d_in[5];
    const float* W_rgb   = (const float*)d_in[6];
    const float* b_rgb   = (const float*)d_in[7];
    float* out = (float*)d_out;

    nerf_render_kernel<<<BLOCKS, 128>>>(rays_o, rays_d, W1, b1, w_sigma, b_sigma,
                                        W_rgb, b_rgb, out);
}